// round 2
// baseline (speedup 1.0000x reference)
#include <cuda_runtime.h>
#include <cuda_bf16.h>
#include <cstdint>

// S4 adaptive embedding: 4 buckets, cutoffs [0,20000,40000,200000,267735]
// d_i = 1024, 256, 64, 16 ; D_PROJ = 1024 ; scale = 32
//
// R2: single fused GEMM launch (all 4 buckets co-scheduled), 64x128 tiles,
// 4x8 per-thread accumulators, double-buffered smem with register prefetch.

#define NTOK 16384
#define DPROJ 1024

__device__ int g_cnt[4];
__device__ int g_tok[4][NTOK];
__device__ int g_idx[4][NTOK];
__device__ int g_is64;

__constant__ int c_D[4] = {1024, 256, 64, 16};

struct Params {
    const float* emb[4];
    const float* proj[4];
    float* out;
};

__global__ void reset_detect_kernel(const void* ids_raw) {
    int t = threadIdx.x;
    if (t < 4) g_cnt[t] = 0;
    // int64 ids (values < 2^31, little-endian) -> every odd 32-bit word is 0.
    const int* w = (const int*)ids_raw;
    int nz = 0;
    for (int i = t; i < 1024; i += 256) nz |= w[2 * i + 1];
    int any = __syncthreads_or(nz);
    if (t == 0) g_is64 = (any == 0) ? 1 : 0;
}

__global__ void bucketize_kernel(const void* ids_raw) {
    int i = blockIdx.x * blockDim.x + threadIdx.x;
    if (i >= NTOK) return;
    long long id;
    if (g_is64) id = ((const long long*)ids_raw)[i];
    else        id = (long long)((const int*)ids_raw)[i];
    int b, l;
    if (id < 20000)       { b = 0; l = 0; }
    else if (id < 40000)  { b = 1; l = 20000; }
    else if (id < 200000) { b = 2; l = 40000; }
    else                  { b = 3; l = 200000; }
    int slot = atomicAdd(&g_cnt[b], 1);
    g_tok[b][slot] = i;
    g_idx[b][slot] = (int)(id - l);
}

// Fused tiled NT-GEMM over all buckets.
// Tile: 64 tokens x 128 dims, 256 threads, per-thread 4 tokens x 8 dims.
// K chunk = 16, double-buffered smem, register prefetch of next chunk.
__global__ void __launch_bounds__(256) fused_gemm_kernel(Params p) {
    const int bucket = blockIdx.z;
    const int n = g_cnt[bucket];
    const int m0 = blockIdx.x * 64;
    if (m0 >= n) return;
    const int n0 = blockIdx.y * 128;
    const int D  = c_D[bucket];
    const float* __restrict__ emb  = p.emb[bucket];
    const float* __restrict__ proj = p.proj[bucket];

    __shared__ float As[2][16][68];    // As[buf][k][m]
    __shared__ float Bs[2][16][132];   // Bs[buf][k][nn]
    __shared__ int s_tok[64];
    __shared__ int s_idx[64];

    const int tid = threadIdx.x;
    if (tid < 64) {
        int m = m0 + tid;
        if (m < n) { s_tok[tid] = g_tok[bucket][m]; s_idx[tid] = g_idx[bucket][m]; }
        else       { s_tok[tid] = -1;               s_idx[tid] = 0; }
    }
    __syncthreads();

    // --- tile-load helpers (per-thread fixed assignment) ---
    // A: 64 rows x 4 float4 = 256 float4 -> 1 per thread
    const int a_m  = tid >> 2;          // 0..63
    const int a_kq = tid & 3;           // 0..3 (float4 within 16-k chunk)
    const size_t a_row = (size_t)s_idx[a_m] * D;
    const bool   a_ok  = (s_tok[a_m] >= 0);
    // B: 128 rows x 4 float4 = 512 float4 -> 2 per thread
    const int b_nn0 = tid >> 2;         // rows tid>>2 and (tid>>2)+64
    const int b_kq  = tid & 3;

    float4 va, vb0, vb1;

    auto ldg_chunk = [&](int k0) {
        va = a_ok ? *(const float4*)&emb[a_row + k0 + a_kq * 4]
                  : make_float4(0.f, 0.f, 0.f, 0.f);
        vb0 = *(const float4*)&proj[(size_t)(n0 + b_nn0)      * D + k0 + b_kq * 4];
        vb1 = *(const float4*)&proj[(size_t)(n0 + b_nn0 + 64) * D + k0 + b_kq * 4];
    };
    auto sts_chunk = [&](int buf) {
        As[buf][a_kq * 4 + 0][a_m] = va.x;
        As[buf][a_kq * 4 + 1][a_m] = va.y;
        As[buf][a_kq * 4 + 2][a_m] = va.z;
        As[buf][a_kq * 4 + 3][a_m] = va.w;
        Bs[buf][b_kq * 4 + 0][b_nn0] = vb0.x;
        Bs[buf][b_kq * 4 + 1][b_nn0] = vb0.y;
        Bs[buf][b_kq * 4 + 2][b_nn0] = vb0.z;
        Bs[buf][b_kq * 4 + 3][b_nn0] = vb0.w;
        Bs[buf][b_kq * 4 + 0][b_nn0 + 64] = vb1.x;
        Bs[buf][b_kq * 4 + 1][b_nn0 + 64] = vb1.y;
        Bs[buf][b_kq * 4 + 2][b_nn0 + 64] = vb1.z;
        Bs[buf][b_kq * 4 + 3][b_nn0 + 64] = vb1.w;
    };

    float acc[4][8] = {};
    const int ty = tid >> 4;   // 0..15 -> 4-token group
    const int tx = tid & 15;   // 0..15 -> 8-dim group

    // prologue
    ldg_chunk(0);
    sts_chunk(0);
    __syncthreads();

    int buf = 0;
    for (int k0 = 0; k0 < D; k0 += 16) {
        const bool has_next = (k0 + 16) < D;
        if (has_next) ldg_chunk(k0 + 16);

        #pragma unroll
        for (int k = 0; k < 16; k++) {
            float a[4], b[8];
            *(float4*)&a[0] = *(const float4*)&As[buf][k][ty * 4];
            *(float4*)&b[0] = *(const float4*)&Bs[buf][k][tx * 8];
            *(float4*)&b[4] = *(const float4*)&Bs[buf][k][tx * 8 + 4];
            #pragma unroll
            for (int i = 0; i < 4; i++)
                #pragma unroll
                for (int j = 0; j < 8; j++)
                    acc[i][j] += a[i] * b[j];
        }

        if (has_next) {
            sts_chunk(buf ^ 1);
            buf ^= 1;
        }
        __syncthreads();
    }

    // epilogue: out[tok][n0 + tx*8 .. +7], fused *32 scale
    #pragma unroll
    for (int i = 0; i < 4; i++) {
        int m   = ty * 4 + i;
        int tok = s_tok[m];
        if (tok >= 0) {
            float* o = &p.out[(size_t)tok * DPROJ + n0 + tx * 8];
            float4 v0 = make_float4(acc[i][0] * 32.f, acc[i][1] * 32.f,
                                    acc[i][2] * 32.f, acc[i][3] * 32.f);
            float4 v1 = make_float4(acc[i][4] * 32.f, acc[i][5] * 32.f,
                                    acc[i][6] * 32.f, acc[i][7] * 32.f);
            *(float4*)&o[0] = v0;
            *(float4*)&o[4] = v1;
        }
    }
}

extern "C" void kernel_launch(void* const* d_in, const int* in_sizes, int n_in,
                              void* d_out, int out_size) {
    Params p;
    const void* ids = d_in[0];
    p.emb[0]  = (const float*)d_in[1];
    p.proj[0] = (const float*)d_in[2];
    p.emb[1]  = (const float*)d_in[3];
    p.proj[1] = (const float*)d_in[4];
    p.emb[2]  = (const float*)d_in[5];
    p.proj[2] = (const float*)d_in[6];
    p.emb[3]  = (const float*)d_in[7];
    p.proj[3] = (const float*)d_in[8];
    p.out = (float*)d_out;

    reset_detect_kernel<<<1, 256>>>(ids);
    bucketize_kernel<<<NTOK / 256, 256>>>(ids);

    dim3 grid(NTOK / 64, DPROJ / 128, 4);  // empty tiles exit on g_cnt check
    fused_gemm_kernel<<<grid, 256>>>(p);
}

// round 4
// speedup vs baseline: 1.8676x; 1.8676x over previous
#include <cuda_runtime.h>
#include <cuda_bf16.h>
#include <cstdint>

// S4 adaptive embedding via warp-level bf16 mma.sync (family-portable PTX).
// out[tok,:] = emb_row(tok) @ proj^T * 32, per bucket.
// fp32 inputs split to bf16 hi/lo; 3-term MMA (AhBh + AlBh + AhBl) -> rel err ~1e-5.
//
// Launches: 1) reset_detect  2) bucketize  3) fused gemm (all buckets).
// GEMM: block tile 128 tok x 128 dim, 512 thr (16 warps, 4x4), warp tile 32x32,
// K-chunk 64, on-the-fly fp32->bf16 hi/lo conversion into 144B-padded smem,
// ldmatrix fragments, m16n8k16 row.col bf16 MMA, scattered float2 epilogue.

#define NTOK  16384
#define DPROJ 1024

__device__ int g_cnt[4];
__device__ int g_tok[4][NTOK];
__device__ int g_idx[4][NTOK];
__device__ int g_is64;

__constant__ int c_D[4] = {1024, 256, 64, 16};

struct Params {
    const float* emb[4];
    const float* proj[4];
    float* out;
};

// ---------------- small setup kernels ----------------
__global__ void reset_detect_kernel(const void* ids_raw) {
    int t = threadIdx.x;
    if (t < 4) g_cnt[t] = 0;
    // int64 ids (values < 2^31, LE) -> every odd 32-bit word is zero.
    const int* w = (const int*)ids_raw;
    int nz = 0;
    for (int i = t; i < 1024; i += 256) nz |= w[2 * i + 1];
    int any = __syncthreads_or(nz);
    if (t == 0) g_is64 = (any == 0) ? 1 : 0;
}

__global__ void bucketize_kernel(const void* ids_raw) {
    int i = blockIdx.x * blockDim.x + threadIdx.x;
    if (i >= NTOK) return;
    long long id;
    if (g_is64) id = ((const long long*)ids_raw)[i];
    else        id = (long long)((const int*)ids_raw)[i];
    int b, l;
    if (id < 20000)       { b = 0; l = 0; }
    else if (id < 40000)  { b = 1; l = 20000; }
    else if (id < 200000) { b = 2; l = 40000; }
    else                  { b = 3; l = 200000; }
    int slot = atomicAdd(&g_cnt[b], 1);
    g_tok[b][slot] = i;
    g_idx[b][slot] = (int)(id - l);
}

// ---------------- MMA helpers (sm_80-portable) ----------------
#define LDSM_X4(r, addr) \
    asm volatile("ldmatrix.sync.aligned.m8n8.x4.shared.b16 {%0,%1,%2,%3}, [%4];" \
        : "=r"((r)[0]), "=r"((r)[1]), "=r"((r)[2]), "=r"((r)[3]) : "r"(addr))

#define MMA_BF16(c, a, b0, b1) \
    asm volatile("mma.sync.aligned.m16n8k16.row.col.f32.bf16.bf16.f32 " \
        "{%0,%1,%2,%3}, {%4,%5,%6,%7}, {%8,%9}, {%0,%1,%2,%3};" \
        : "+f"((c)[0]), "+f"((c)[1]), "+f"((c)[2]), "+f"((c)[3]) \
        : "r"((a)[0]), "r"((a)[1]), "r"((a)[2]), "r"((a)[3]), "r"(b0), "r"(b1))

__device__ __forceinline__ uint32_t smem_u32(const void* p) {
    uint32_t a;
    asm("{ .reg .u64 t; cvta.to.shared.u64 t, %1; cvt.u32.u64 %0, t; }" : "=r"(a) : "l"(p));
    return a;
}

__device__ __forceinline__ uint32_t pack_hi(float x, float y) {
    __nv_bfloat162 t;
    t.x = __float2bfloat16(x);
    t.y = __float2bfloat16(y);
    return *reinterpret_cast<uint32_t*>(&t);
}
__device__ __forceinline__ uint32_t pack_lo(float x, float y) {
    __nv_bfloat16 hx = __float2bfloat16(x), hy = __float2bfloat16(y);
    __nv_bfloat162 t;
    t.x = __float2bfloat16(x - __bfloat162float(hx));
    t.y = __float2bfloat16(y - __bfloat162float(hy));
    return *reinterpret_cast<uint32_t*>(&t);
}

// smem layout (bytes): 4 tiles of 128 rows x 144B (72 bf16, 64 used):
//   A_hi @ 0, A_lo @ 18432, B_hi @ 36864, B_lo @ 55296 ; s_tok @ 73728 ; s_idx @ 74240
#define ROWB   144
#define SM_AH  0
#define SM_AL  18432
#define SM_BH  36864
#define SM_BL  55296
#define SM_TOK 73728
#define SM_IDX 74240
#define GEMM_SMEM 74752

__global__ void __launch_bounds__(512, 1) gemm_kernel(Params p) {
    extern __shared__ char sm[];
    int* s_tok = (int*)(sm + SM_TOK);
    int* s_idx = (int*)(sm + SM_IDX);
    const int tid  = threadIdx.x;
    const int lane = tid & 31;
    const int wid  = tid >> 5;
    const int wm   = wid >> 2;       // 0..3 -> 32-token strip
    const int wn   = wid & 3;        // 0..3 -> 32-dim strip

    // map blockIdx.x -> (bucket, mtile)
    int cnt0 = g_cnt[0], cnt1 = g_cnt[1], cnt2 = g_cnt[2], cnt3 = g_cnt[3];
    int t0 = (cnt0 + 127) >> 7, t1 = (cnt1 + 127) >> 7, t2 = (cnt2 + 127) >> 7;
    int x = blockIdx.x, b, n;
    if (x < t0)              { b = 0; n = cnt0; }
    else if ((x -= t0) < t1) { b = 1; n = cnt1; }
    else if ((x -= t1) < t2) { b = 2; n = cnt2; }
    else                     { b = 3; n = cnt3; x -= t2; if (x >= ((cnt3 + 127) >> 7)) return; }
    const int m0 = x << 7;
    const int n0 = blockIdx.y << 7;
    const int D  = c_D[b];
    const float* __restrict__ emb  = p.emb[b];
    const float* __restrict__ proj = p.proj[b];

    if (tid < 128) {
        int m = m0 + tid;
        if (m < n) { s_tok[tid] = g_tok[b][m]; s_idx[tid] = g_idx[b][m]; }
        else       { s_tok[tid] = -1;          s_idx[tid] = 0; }
    }
    __syncthreads();

    float acc[2][4][4] = {};       // [fm][fn][reg]
    const uint32_t sb = smem_u32(sm);

    // ldmatrix per-lane address pieces
    const uint32_t a_row = wm * 32 + (lane & 15);
    const uint32_t a_kof = ((lane >> 1) & 8);           // +8 cols for lanes 16..31
    const int g = lane >> 3;
    const uint32_t b_rof = ((g >> 1) & 1) * 8 + (lane & 7);
    const uint32_t b_kof = (g & 1) * 8;

    const int nchunks = (D + 63) >> 6;
    for (int ck = 0; ck < nchunks; ck++) {
        __syncthreads();     // previous iter's frag reads done before overwrite
        // ---- stage chunk: A (gathered emb) and B (proj rows), fp32 -> bf16 hi/lo ----
        #pragma unroll
        for (int i = 0; i < 4; i++) {
            int f = tid + i * 512;          // 2048 float4 slots: 128 rows x 16
            int r = f >> 4, q = f & 15;
            int kcol = (ck << 6) + q * 4;
            if (kcol < D) {
                float4 va = *(const float4*)(emb + (size_t)s_idx[r] * D + kcol);
                uint2 h = make_uint2(pack_hi(va.x, va.y), pack_hi(va.z, va.w));
                uint2 l = make_uint2(pack_lo(va.x, va.y), pack_lo(va.z, va.w));
                *(uint2*)(sm + SM_AH + r * ROWB + q * 8) = h;
                *(uint2*)(sm + SM_AL + r * ROWB + q * 8) = l;
                float4 vb = *(const float4*)(proj + (size_t)(n0 + r) * D + kcol);
                uint2 hb = make_uint2(pack_hi(vb.x, vb.y), pack_hi(vb.z, vb.w));
                uint2 lb = make_uint2(pack_lo(vb.x, vb.y), pack_lo(vb.z, vb.w));
                *(uint2*)(sm + SM_BH + r * ROWB + q * 8) = hb;
                *(uint2*)(sm + SM_BL + r * ROWB + q * 8) = lb;
            }
        }
        __syncthreads();

        const int kst = ((D - (ck << 6)) < 64 ? (D - (ck << 6)) : 64) >> 4;
        for (int ks = 0; ks < kst; ks++) {
            const uint32_t kbase = (ks * 16) * 2;
            // A fragments: [part][fm][4]
            uint32_t af[2][2][4];
            #pragma unroll
            for (int fm = 0; fm < 2; fm++) {
                uint32_t off = (a_row + fm * 16) * ROWB + kbase + a_kof * 2;
                LDSM_X4(af[0][fm], sb + SM_AH + off);
                LDSM_X4(af[1][fm], sb + SM_AL + off);
            }
            // B fragments: x4 covers n16 x k16 -> regs [b0(n8a),b1(n8a),b0(n8b),b1(n8b)]
            uint32_t bf[2][2][4];
            #pragma unroll
            for (int fn2 = 0; fn2 < 2; fn2++) {
                uint32_t off = (wn * 32 + fn2 * 16 + b_rof) * ROWB + kbase + b_kof * 2;
                LDSM_X4(bf[0][fn2], sb + SM_BH + off);
                LDSM_X4(bf[1][fn2], sb + SM_BL + off);
            }
            #pragma unroll
            for (int fm = 0; fm < 2; fm++)
                #pragma unroll
                for (int fn = 0; fn < 4; fn++) {
                    uint32_t b0h = bf[0][fn >> 1][(fn & 1) * 2];
                    uint32_t b1h = bf[0][fn >> 1][(fn & 1) * 2 + 1];
                    uint32_t b0l = bf[1][fn >> 1][(fn & 1) * 2];
                    uint32_t b1l = bf[1][fn >> 1][(fn & 1) * 2 + 1];
                    MMA_BF16(acc[fm][fn], af[0][fm], b0h, b1h);   // Ah*Bh
                    MMA_BF16(acc[fm][fn], af[1][fm], b0h, b1h);   // Al*Bh
                    MMA_BF16(acc[fm][fn], af[0][fm], b0l, b1l);   // Ah*Bl
                }
        }
    }

    // ---- epilogue: scatter rows, fused *32 ----
    #pragma unroll
    for (int fm = 0; fm < 2; fm++) {
        int r0 = wm * 32 + fm * 16 + (lane >> 2);
        int tokA = s_tok[r0];
        int tokB = s_tok[r0 + 8];
        #pragma unroll
        for (int fn = 0; fn < 4; fn++) {
            int c = n0 + wn * 32 + fn * 8 + (lane & 3) * 2;
            if (tokA >= 0)
                *(float2*)(p.out + (size_t)tokA * DPROJ + c) =
                    make_float2(acc[fm][fn][0] * 32.f, acc[fm][fn][1] * 32.f);
            if (tokB >= 0)
                *(float2*)(p.out + (size_t)tokB * DPROJ + c) =
                    make_float2(acc[fm][fn][2] * 32.f, acc[fm][fn][3] * 32.f);
        }
    }
}

extern "C" void kernel_launch(void* const* d_in, const int* in_sizes, int n_in,
                              void* d_out, int out_size) {
    Params p;
    const void* ids = d_in[0];
    p.emb[0]  = (const float*)d_in[1];
    p.proj[0] = (const float*)d_in[2];
    p.emb[1]  = (const float*)d_in[3];
    p.proj[1] = (const float*)d_in[4];
    p.emb[2]  = (const float*)d_in[5];
    p.proj[2] = (const float*)d_in[6];
    p.emb[3]  = (const float*)d_in[7];
    p.proj[3] = (const float*)d_in[8];
    p.out = (float*)d_out;

    cudaFuncSetAttribute(gemm_kernel, cudaFuncAttributeMaxDynamicSharedMemorySize, GEMM_SMEM);

    reset_detect_kernel<<<1, 256>>>(ids);
    bucketize_kernel<<<NTOK / 256, 256>>>(ids);
    gemm_kernel<<<dim3(131, DPROJ / 128), 512, GEMM_SMEM>>>(p);
}

// round 5
// speedup vs baseline: 2.1677x; 1.1607x over previous
#include <cuda_runtime.h>
#include <cuda_bf16.h>
#include <cstdint>

// S4 adaptive embedding: bf16 hi/lo split mma.sync, cp.async double-buffered GEMM.
// out[tok,:] = emb_row(tok) @ proj^T * 32 per bucket; 3-term MMA -> rel err ~5e-6.
//
// Launches:
//  1) reset_detect 2) bucketize 3) conv_proj 4) gather_emb 5) gemm
// Packed bf16 hi/lo layouts (zero-padded K): Dpad = {1024,256,64,64}.

#define NTOK  16384
#define DPROJ 1024
#define KSUM  1408              // 1024+256+64+64

__device__ int g_cnt[4];
__device__ int g_tok[4][NTOK];
__device__ int g_idx[4][NTOK];
__device__ int g_is64;

// +128 row pad: tail tiles of the last bucket may read past slot cnt
__device__ __nv_bfloat16 g_embH[(size_t)(NTOK + 128) * KSUM];
__device__ __nv_bfloat16 g_embL[(size_t)(NTOK + 128) * KSUM];
__device__ __nv_bfloat16 g_projH[(size_t)DPROJ * KSUM];
__device__ __nv_bfloat16 g_projL[(size_t)DPROJ * KSUM];

__constant__ int c_D[4]    = {1024, 256, 64, 16};
__constant__ int c_Dpad[4] = {1024, 256, 64, 64};
__constant__ int c_lgD[4]  = {10, 8, 6, 4};
__constant__ int c_KO[4]   = {0, 1024, 1280, 1344};   // packed K offset per bucket

struct Params {
    const float* emb[4];
    const float* proj[4];
    float* out;
};

// ---------------- setup kernels ----------------
__global__ void reset_detect_kernel(const void* ids_raw) {
    int t = threadIdx.x;
    if (t < 4) g_cnt[t] = 0;
    const int* w = (const int*)ids_raw;     // first 8KB safe for both layouts
    int nz = 0;
    for (int i = t; i < 1024; i += 256) nz |= w[2 * i + 1];
    int any = __syncthreads_or(nz);
    if (t == 0) g_is64 = (any == 0) ? 1 : 0;
}

__global__ void bucketize_kernel(const void* ids_raw) {
    int i = blockIdx.x * blockDim.x + threadIdx.x;
    if (i >= NTOK) return;
    long long id;
    if (g_is64) id = ((const long long*)ids_raw)[i];
    else        id = (long long)((const int*)ids_raw)[i];
    int b, l;
    if (id < 20000)       { b = 0; l = 0; }
    else if (id < 40000)  { b = 1; l = 20000; }
    else if (id < 200000) { b = 2; l = 40000; }
    else                  { b = 3; l = 200000; }
    int slot = atomicAdd(&g_cnt[b], 1);
    g_tok[b][slot] = i;
    g_idx[b][slot] = (int)(id - l);
}

__global__ void conv_proj_kernel(Params p) {
    int gid = blockIdx.x * 256 + threadIdx.x;
    if (gid >= DPROJ * KSUM) return;
    int d = gid / KSUM, kk = gid - d * KSUM;
    int b, k;
    if (kk < 1024)      { b = 0; k = kk; }
    else if (kk < 1280) { b = 1; k = kk - 1024; }
    else if (kk < 1344) { b = 2; k = kk - 1280; }
    else                { b = 3; k = kk - 1344; }
    int D = c_D[b];
    if (k >= D) return;                            // pads stay zero
    float xv = p.proj[b][(size_t)d * D + k];
    __nv_bfloat16 h = __float2bfloat16(xv);
    size_t o = (size_t)c_KO[b] * DPROJ + (size_t)d * c_Dpad[b] + k;
    g_projH[o] = h;
    g_projL[o] = __float2bfloat16(xv - __bfloat162float(h));
}

__global__ void gather_emb_kernel(Params p) {
    int b = blockIdx.y;
    int cnt = g_cnt[b], D = c_D[b], lg = c_lgD[b], Dpad = c_Dpad[b];
    const float* src = p.emb[b];
    size_t base = (size_t)c_KO[b] * (NTOK + 128);
    int total = cnt << lg;
    for (int t = blockIdx.x * 256 + threadIdx.x; t < total; t += gridDim.x * 256) {
        int slot = t >> lg, k = t & (D - 1);
        float xv = src[((size_t)g_idx[b][slot] << lg) + k];
        __nv_bfloat16 h = __float2bfloat16(xv);
        size_t o = base + (size_t)slot * Dpad + k;
        g_embH[o] = h;
        g_embL[o] = __float2bfloat16(xv - __bfloat162float(h));
    }
}

// ---------------- MMA / async helpers ----------------
#define LDSM_X4(r, addr) \
    asm volatile("ldmatrix.sync.aligned.m8n8.x4.shared.b16 {%0,%1,%2,%3}, [%4];" \
        : "=r"((r)[0]), "=r"((r)[1]), "=r"((r)[2]), "=r"((r)[3]) : "r"(addr))

#define MMA_BF16(c, a, b0, b1) \
    asm volatile("mma.sync.aligned.m16n8k16.row.col.f32.bf16.bf16.f32 " \
        "{%0,%1,%2,%3}, {%4,%5,%6,%7}, {%8,%9}, {%0,%1,%2,%3};" \
        : "+f"((c)[0]), "+f"((c)[1]), "+f"((c)[2]), "+f"((c)[3]) \
        : "r"((a)[0]), "r"((a)[1]), "r"((a)[2]), "r"((a)[3]), "r"(b0), "r"(b1))

#define CP_ASYNC16(dst, src) \
    asm volatile("cp.async.cg.shared.global [%0], [%1], 16;" :: "r"(dst), "l"(src) : "memory")
#define CP_COMMIT() asm volatile("cp.async.commit_group;" ::: "memory")
#define CP_WAIT(n)  asm volatile("cp.async.wait_group %0;" :: "n"(n) : "memory")

__device__ __forceinline__ uint32_t smem_u32(const void* p) {
    uint32_t a;
    asm("{ .reg .u64 t; cvta.to.shared.u64 t, %1; cvt.u32.u64 %0, t; }" : "=r"(a) : "l"(p));
    return a;
}

// smem: per buf 4 parts (AH,AL,BH,BL) of 128 rows x 144B
#define ROWB   144
#define PARTB  18432            // 128*144
#define BUFB   73728            // 4 parts
#define SM_TOK 147456
#define SM_IDXU 147968
#define GEMM_SMEM 148480

__global__ void __launch_bounds__(512, 1) gemm_kernel(Params p) {
    extern __shared__ char sm[];
    int* s_tok = (int*)(sm + SM_TOK);
    const int tid  = threadIdx.x;
    const int lane = tid & 31;
    const int wid  = tid >> 5;
    const int wm   = wid >> 2;
    const int wn   = wid & 3;

    int cnt0 = g_cnt[0], cnt1 = g_cnt[1], cnt2 = g_cnt[2], cnt3 = g_cnt[3];
    int t0 = (cnt0 + 127) >> 7, t1 = (cnt1 + 127) >> 7, t2 = (cnt2 + 127) >> 7;
    int x = blockIdx.x, b, n;
    if (x < t0)              { b = 0; n = cnt0; }
    else if ((x -= t0) < t1) { b = 1; n = cnt1; }
    else if ((x -= t1) < t2) { b = 2; n = cnt2; }
    else                     { b = 3; n = cnt3; x -= t2; if (x >= ((cnt3 + 127) >> 7)) return; }
    const int m0 = x << 7;
    const int n0 = blockIdx.y << 7;
    const int Dpad = c_Dpad[b];
    const int nc = Dpad >> 6;

    if (tid < 128) {
        int m = m0 + tid;
        s_tok[tid] = (m < n) ? g_tok[b][m] : -1;
    }

    // part source bases (bf16, packed)
    const __nv_bfloat16* baseP[4];
    {
        size_t eo = (size_t)c_KO[b] * (NTOK + 128) + (size_t)m0 * Dpad;
        size_t po = (size_t)c_KO[b] * DPROJ + (size_t)n0 * Dpad;
        baseP[0] = g_embH + eo;
        baseP[1] = g_embL + eo;
        baseP[2] = g_projH + po;
        baseP[3] = g_projL + po;
    }
    const uint32_t sb = smem_u32(sm);

    // 8 cp.async of 16B per thread per chunk (4096 total = 4 parts x 128 rows x 8)
    auto issue = [&](int ck, int buf) {
        #pragma unroll
        for (int i = 0; i < 8; i++) {
            int f = tid + i * 512;
            int part = f >> 10, rem = f & 1023, r = rem >> 3, q = rem & 7;
            const __nv_bfloat16* src = baseP[part] + (size_t)r * Dpad + (ck << 6) + (q << 3);
            uint32_t dst = sb + buf * BUFB + part * PARTB + r * ROWB + (q << 4);
            CP_ASYNC16(dst, src);
        }
        CP_COMMIT();
    };

    float acc[2][4][4] = {};

    const uint32_t a_row = wm * 32 + (lane & 15);
    const uint32_t a_kof = ((lane >> 1) & 8);
    const int g = lane >> 3;
    const uint32_t b_rof = ((g >> 1) & 1) * 8 + (lane & 7);
    const uint32_t b_kof = (g & 1) * 8;

    issue(0, 0);
    for (int ck = 0; ck < nc; ck++) {
        const int buf = ck & 1;
        if (ck + 1 < nc) { issue(ck + 1, buf ^ 1); CP_WAIT(1); }
        else             { CP_WAIT(0); }
        __syncthreads();

        const uint32_t bufb = sb + buf * BUFB;
        #pragma unroll
        for (int ks = 0; ks < 4; ks++) {
            const uint32_t kbase = ks * 32;
            uint32_t af[2][2][4];
            #pragma unroll
            for (int fm = 0; fm < 2; fm++) {
                uint32_t off = (a_row + fm * 16) * ROWB + kbase + a_kof * 2;
                LDSM_X4(af[0][fm], bufb + off);              // AH
                LDSM_X4(af[1][fm], bufb + PARTB + off);      // AL
            }
            uint32_t bfr[2][2][4];
            #pragma unroll
            for (int fn2 = 0; fn2 < 2; fn2++) {
                uint32_t off = (wn * 32 + fn2 * 16 + b_rof) * ROWB + kbase + b_kof * 2;
                LDSM_X4(bfr[0][fn2], bufb + 2 * PARTB + off);  // BH
                LDSM_X4(bfr[1][fn2], bufb + 3 * PARTB + off);  // BL
            }
            #pragma unroll
            for (int fm = 0; fm < 2; fm++)
                #pragma unroll
                for (int fn = 0; fn < 4; fn++) {
                    uint32_t b0h = bfr[0][fn >> 1][(fn & 1) * 2];
                    uint32_t b1h = bfr[0][fn >> 1][(fn & 1) * 2 + 1];
                    uint32_t b0l = bfr[1][fn >> 1][(fn & 1) * 2];
                    uint32_t b1l = bfr[1][fn >> 1][(fn & 1) * 2 + 1];
                    MMA_BF16(acc[fm][fn], af[0][fm], b0h, b1h);
                    MMA_BF16(acc[fm][fn], af[1][fm], b0h, b1h);
                    MMA_BF16(acc[fm][fn], af[0][fm], b0l, b1l);
                }
        }
        __syncthreads();
    }

    #pragma unroll
    for (int fm = 0; fm < 2; fm++) {
        int r0 = wm * 32 + fm * 16 + (lane >> 2);
        int tokA = s_tok[r0];
        int tokB = s_tok[r0 + 8];
        #pragma unroll
        for (int fn = 0; fn < 4; fn++) {
            int c = n0 + wn * 32 + fn * 8 + (lane & 3) * 2;
            if (tokA >= 0)
                *(float2*)(p.out + (size_t)tokA * DPROJ + c) =
                    make_float2(acc[fm][fn][0] * 32.f, acc[fm][fn][1] * 32.f);
            if (tokB >= 0)
                *(float2*)(p.out + (size_t)tokB * DPROJ + c) =
                    make_float2(acc[fm][fn][2] * 32.f, acc[fm][fn][3] * 32.f);
        }
    }
}

extern "C" void kernel_launch(void* const* d_in, const int* in_sizes, int n_in,
                              void* d_out, int out_size) {
    Params p;
    const void* ids = d_in[0];
    p.emb[0]  = (const float*)d_in[1];
    p.proj[0] = (const float*)d_in[2];
    p.emb[1]  = (const float*)d_in[3];
    p.proj[1] = (const float*)d_in[4];
    p.emb[2]  = (const float*)d_in[5];
    p.proj[2] = (const float*)d_in[6];
    p.emb[3]  = (const float*)d_in[7];
    p.proj[3] = (const float*)d_in[8];
    p.out = (float*)d_out;

    cudaFuncSetAttribute(gemm_kernel, cudaFuncAttributeMaxDynamicSharedMemorySize, GEMM_SMEM);

    reset_detect_kernel<<<1, 256>>>(ids);
    bucketize_kernel<<<NTOK / 256, 256>>>(ids);
    conv_proj_kernel<<<(DPROJ * KSUM + 255) / 256, 256>>>(p);
    gather_emb_kernel<<<dim3(192, 4), 256>>>(p);
    gemm_kernel<<<dim3(131, DPROJ / 128), 512, GEMM_SMEM>>>(p);
}

// round 9
// speedup vs baseline: 2.8561x; 1.3176x over previous
#include <cuda_runtime.h>
#include <cuda_bf16.h>
#include <cstdint>

// S4 adaptive embedding: bf16 hi/lo split mma.sync + cp.async.bulk staged GEMM.
// out[tok,:] = emb_row(tok) @ proj^T * 32 per bucket; 3-term MMA -> rel err ~5e-6.
//
// Packed bf16 arrays are PRE-TILED and PRE-SWIZZLED in gmem:
//   per (tile128, chunk64k): contiguous 16KB block, rows 128B, SW128 swizzle.
// GEMM stages each chunk with 4x cp.async.bulk (16KB) + mbarrier, TRIPLE-buffered.
// Launches: conv_proj(+zero cnt) -> bucketize(+detect) -> gather_emb -> gemm.

#define NTOK  16384
#define NTOKP 16512             // +128 pad rows for tail tiles
#define DPROJ 1024

__device__ int g_cnt[4];
__device__ int g_tok[4][NTOK];
__device__ int g_idx[4][NTOK];

__device__ alignas(128) __nv_bfloat16 g_embH[(size_t)NTOKP * 1408];
__device__ alignas(128) __nv_bfloat16 g_embL[(size_t)NTOKP * 1408];
__device__ alignas(128) __nv_bfloat16 g_projH[(size_t)DPROJ * 1408];
__device__ alignas(128) __nv_bfloat16 g_projL[(size_t)DPROJ * 1408];

__constant__ int c_D[4]    = {1024, 256, 64, 16};
__constant__ int c_Dpad[4] = {1024, 256, 64, 64};
__constant__ int c_lgD[4]  = {10, 8, 6, 4};
__constant__ int c_KO[4]   = {0, 1024, 1280, 1344};
__constant__ int c_KS[4]   = {4, 4, 4, 1};          // k16-steps per chunk (b3: K=16 only)

struct Params {
    const float* emb[4];
    const float* proj[4];
    float* out;
};

__device__ __forceinline__ uint32_t swz(uint32_t off) { return off ^ ((off >> 3) & 0x70); }

__device__ __forceinline__ uint32_t pack_hi(float x, float y) {
    __nv_bfloat162 t;
    t.x = __float2bfloat16(x);
    t.y = __float2bfloat16(y);
    return *reinterpret_cast<uint32_t*>(&t);
}
__device__ __forceinline__ uint32_t pack_lo(float x, float y) {
    __nv_bfloat16 hx = __float2bfloat16(x), hy = __float2bfloat16(y);
    __nv_bfloat162 t;
    t.x = __float2bfloat16(x - __bfloat162float(hx));
    t.y = __float2bfloat16(y - __bfloat162float(hy));
    return *reinterpret_cast<uint32_t*>(&t);
}

// ---------------- prepasses ----------------
// proj fp32 -> pre-tiled/swizzled bf16 hi/lo. Also zeroes bucket counters.
__global__ void conv_proj_kernel(Params p) {
    if (blockIdx.x == 0 && blockIdx.y == 0 && threadIdx.x < 4) g_cnt[threadIdx.x] = 0;
    int b = blockIdx.y;
    int D = c_D[b], lgG = c_lgD[b] - 3, G = 1 << lgG, ncb = c_Dpad[b] >> 6;
    const float* src = p.proj[b];
    size_t PB = 2ull * c_KO[b] * DPROJ;   // byte base
    int total = DPROJ << lgG;
    for (int t = blockIdx.x * 256 + threadIdx.x; t < total; t += gridDim.x * 256) {
        int d = t >> lgG, g8 = t & (G - 1);
        int k0 = g8 << 3;
        const float* s = src + (size_t)d * D + k0;
        float4 va = *(const float4*)s, vb2 = *(const float4*)(s + 4);
        uint4 H = make_uint4(pack_hi(va.x, va.y), pack_hi(va.z, va.w),
                             pack_hi(vb2.x, vb2.y), pack_hi(vb2.z, vb2.w));
        uint4 L = make_uint4(pack_lo(va.x, va.y), pack_lo(va.z, va.w),
                             pack_lo(vb2.x, vb2.y), pack_lo(vb2.z, vb2.w));
        int nt = d >> 7, r = d & 127, ck = k0 >> 6;
        size_t off = PB + (size_t)(nt * ncb + ck) * 16384
                        + swz((uint32_t)(r * 128 + ((g8 & 7) << 4)));
        *(uint4*)((char*)g_projH + off) = H;
        *(uint4*)((char*)g_projL + off) = L;
    }
}

// bucketize with per-launch id-layout detection (first 2KB is safe for both layouts)
__global__ void bucketize_kernel(const void* ids_raw) {
    const int* w = (const int*)ids_raw;
    int nz = w[2 * threadIdx.x + 1];          // odd words of first 256 slots
    int is64 = (__syncthreads_or(nz) == 0);
    int i = blockIdx.x * 256 + threadIdx.x;
    long long id = is64 ? ((const long long*)ids_raw)[i] : (long long)w[i];
    int b, l;
    if (id < 20000)       { b = 0; l = 0; }
    else if (id < 40000)  { b = 1; l = 20000; }
    else if (id < 200000) { b = 2; l = 40000; }
    else                  { b = 3; l = 200000; }
    int slot = atomicAdd(&g_cnt[b], 1);
    g_tok[b][slot] = i;
    g_idx[b][slot] = (int)(id - l);
}

// gathered emb rows fp32 -> pre-tiled/swizzled bf16 hi/lo
__global__ void gather_emb_kernel(Params p) {
    int b = blockIdx.y;
    int cnt = g_cnt[b], D = c_D[b], lgG = c_lgD[b] - 3, G = 1 << lgG, ncb = c_Dpad[b] >> 6;
    const float* src = p.emb[b];
    size_t AB = 2ull * c_KO[b] * NTOKP;
    int total = cnt << lgG;
    for (int t = blockIdx.x * 256 + threadIdx.x; t < total; t += gridDim.x * 256) {
        int slot = t >> lgG, g8 = t & (G - 1);
        int k0 = g8 << 3;
        const float* s = src + (size_t)g_idx[b][slot] * D + k0;
        float4 va = *(const float4*)s, vb2 = *(const float4*)(s + 4);
        uint4 H = make_uint4(pack_hi(va.x, va.y), pack_hi(va.z, va.w),
                             pack_hi(vb2.x, vb2.y), pack_hi(vb2.z, vb2.w));
        uint4 L = make_uint4(pack_lo(va.x, va.y), pack_lo(va.z, va.w),
                             pack_lo(vb2.x, vb2.y), pack_lo(vb2.z, vb2.w));
        int mt = slot >> 7, r = slot & 127, ck = k0 >> 6;
        size_t off = AB + (size_t)(mt * ncb + ck) * 16384
                        + swz((uint32_t)(r * 128 + ((g8 & 7) << 4)));
        *(uint4*)((char*)g_embH + off) = H;
        *(uint4*)((char*)g_embL + off) = L;
    }
}

// ---------------- MMA / bulk-copy helpers ----------------
#define LDSM_X4(r, addr) \
    asm volatile("ldmatrix.sync.aligned.m8n8.x4.shared.b16 {%0,%1,%2,%3}, [%4];" \
        : "=r"((r)[0]), "=r"((r)[1]), "=r"((r)[2]), "=r"((r)[3]) : "r"(addr))

#define MMA_BF16(c, a, b0, b1) \
    asm volatile("mma.sync.aligned.m16n8k16.row.col.f32.bf16.bf16.f32 " \
        "{%0,%1,%2,%3}, {%4,%5,%6,%7}, {%8,%9}, {%0,%1,%2,%3};" \
        : "+f"((c)[0]), "+f"((c)[1]), "+f"((c)[2]), "+f"((c)[3]) \
        : "r"((a)[0]), "r"((a)[1]), "r"((a)[2]), "r"((a)[3]), "r"(b0), "r"(b1))

#define CP_BULK(dst, src, bytes, mbar) \
    asm volatile("cp.async.bulk.shared::cta.global.mbarrier::complete_tx::bytes [%0], [%1], %2, [%3];" \
        :: "r"(dst), "l"(src), "r"((uint32_t)(bytes)), "r"(mbar) : "memory")
#define MBAR_INIT(a, c) \
    asm volatile("mbarrier.init.shared.b64 [%0], %1;" :: "r"(a), "r"((uint32_t)(c)) : "memory")
#define MBAR_EXPECT(a, n) \
    asm volatile("mbarrier.arrive.expect_tx.shared.b64 _, [%0], %1;" :: "r"(a), "r"((uint32_t)(n)) : "memory")
#define MBAR_WAIT(a, ph) do { \
    uint32_t _m = (a), _p = (ph), _d; \
    asm volatile("{ .reg .pred p; mbarrier.try_wait.parity.acquire.cta.shared::cta.b64 p, [%1], %2; selp.b32 %0,1,0,p; }" \
        : "=r"(_d) : "r"(_m), "r"(_p) : "memory"); \
    if (!_d) { \
        asm volatile("{ .reg .pred P1; WL_%=: mbarrier.try_wait.parity.acquire.cta.shared::cta.b64 P1, [%0], %1, 0x989680; " \
                     "@P1 bra.uni WD_%=; bra.uni WL_%=; WD_%=: }" :: "r"(_m), "r"(_p) : "memory"); \
    } } while (0)

__device__ __forceinline__ uint32_t smem_u32(const void* p) {
    uint32_t a;
    asm("{ .reg .u64 t; cvta.to.shared.u64 t, %1; cvt.u32.u64 %0, t; }" : "=r"(a) : "l"(p));
    return a;
}

// smem: buf{0,1,2} x parts{AH,AL,BH,BL} x 16KB ; s_tok ; mbars
#define PARTB  16384
#define BUFB   65536
#define NBUF   3
#define SM_TOK  196608
#define SM_MBAR 197120
#define GEMM_SMEM 197184

__global__ void __launch_bounds__(512, 1) gemm_kernel(Params p) {
    extern __shared__ __align__(1024) char sm[];
    int* s_tok = (int*)(sm + SM_TOK);
    const int tid  = threadIdx.x;
    const int lane = tid & 31;
    const int wid  = tid >> 5;
    const int wm   = wid >> 2;
    const int wn   = wid & 3;

    int cnt0 = g_cnt[0], cnt1 = g_cnt[1], cnt2 = g_cnt[2], cnt3 = g_cnt[3];
    int t0 = (cnt0 + 127) >> 7, t1 = (cnt1 + 127) >> 7, t2 = (cnt2 + 127) >> 7;
    int x = blockIdx.x, b, n;
    if (x < t0)              { b = 0; n = cnt0; }
    else if ((x -= t0) < t1) { b = 1; n = cnt1; }
    else if ((x -= t1) < t2) { b = 2; n = cnt2; }
    else                     { b = 3; n = cnt3; x -= t2; if (x >= ((cnt3 + 127) >> 7)) return; }
    const int mt = x;
    const int m0 = mt << 7;
    const int nt = blockIdx.y;
    const int n0 = nt << 7;
    const int ncb = c_Dpad[b] >> 6;
    const int ksteps = c_KS[b];

    if (tid < 128) {
        int m = m0 + tid;
        s_tok[tid] = (m < n) ? g_tok[b][m] : -1;
    }

    // chunk-contiguous 16KB sources
    const char* pAH = (const char*)g_embH + 2ull * c_KO[b] * NTOKP + (size_t)mt * ncb * PARTB;
    const char* pAL = (const char*)g_embL + 2ull * c_KO[b] * NTOKP + (size_t)mt * ncb * PARTB;
    const char* pBH = (const char*)g_projH + 2ull * c_KO[b] * DPROJ + (size_t)nt * ncb * PARTB;
    const char* pBL = (const char*)g_projL + 2ull * c_KO[b] * DPROJ + (size_t)nt * ncb * PARTB;

    const uint32_t sb = smem_u32(sm);
    if (tid == 0) {
        MBAR_INIT(sb + SM_MBAR,      1);
        MBAR_INIT(sb + SM_MBAR + 8,  1);
        MBAR_INIT(sb + SM_MBAR + 16, 1);
    }
    __syncthreads();

    auto issue = [&](int ck, int buf) {
        uint32_t mb = sb + SM_MBAR + buf * 8;
        MBAR_EXPECT(mb, 4 * PARTB);
        uint32_t d = sb + buf * BUFB;
        size_t co = (size_t)ck * PARTB;
        CP_BULK(d,             pAH + co, PARTB, mb);
        CP_BULK(d + PARTB,     pAL + co, PARTB, mb);
        CP_BULK(d + 2 * PARTB, pBH + co, PARTB, mb);
        CP_BULK(d + 3 * PARTB, pBL + co, PARTB, mb);
    };

    if (tid == 0) {
        issue(0, 0);
        if (ncb > 1) issue(1, 1);
    }

    float acc[2][4][4] = {};
    const uint32_t a_row = wm * 32 + (lane & 15);
    const uint32_t a_kof = ((lane >> 1) & 8);
    const int g = lane >> 3;
    const uint32_t b_rof = ((g >> 1) & 1) * 8 + (lane & 7);
    const uint32_t b_kof = (g & 1) * 8;

    int ph[NBUF] = {0, 0, 0};
    int buf = 0;
    for (int ck = 0; ck < ncb; ck++) {
        // issue ck+2 into buffer (ck+2)%3: its readers finished at end of ck-1
        if (ck + 2 < ncb && tid == 0) {
            int nb = buf + 2;
            if (nb >= NBUF) nb -= NBUF;
            issue(ck + 2, nb);
        }
        MBAR_WAIT(sb + SM_MBAR + buf * 8, ph[buf]);
        ph[buf] ^= 1;

        const uint32_t bufb = sb + buf * BUFB;
        #pragma unroll 4
        for (int ks = 0; ks < ksteps; ks++) {
            const uint32_t kbase = ks * 32;
            uint32_t af[2][2][4];
            #pragma unroll
            for (int fm = 0; fm < 2; fm++) {
                uint32_t off = swz((a_row + fm * 16) * 128 + kbase + a_kof * 2);
                LDSM_X4(af[0][fm], bufb + off);              // AH
                LDSM_X4(af[1][fm], bufb + PARTB + off);      // AL
            }
            uint32_t bfr[2][2][4];
            #pragma unroll
            for (int fn2 = 0; fn2 < 2; fn2++) {
                uint32_t off = swz((wn * 32 + fn2 * 16 + b_rof) * 128 + kbase + b_kof * 2);
                LDSM_X4(bfr[0][fn2], bufb + 2 * PARTB + off);  // BH
                LDSM_X4(bfr[1][fn2], bufb + 3 * PARTB + off);  // BL
            }
            #pragma unroll
            for (int fm = 0; fm < 2; fm++)
                #pragma unroll
                for (int fn = 0; fn < 4; fn++) {
                    uint32_t b0h = bfr[0][fn >> 1][(fn & 1) * 2];
                    uint32_t b1h = bfr[0][fn >> 1][(fn & 1) * 2 + 1];
                    uint32_t b0l = bfr[1][fn >> 1][(fn & 1) * 2];
                    uint32_t b1l = bfr[1][fn >> 1][(fn & 1) * 2 + 1];
                    MMA_BF16(acc[fm][fn], af[0][fm], b0h, b1h);
                    MMA_BF16(acc[fm][fn], af[1][fm], b0h, b1h);
                    MMA_BF16(acc[fm][fn], af[0][fm], b0l, b1l);
                }
        }
        __syncthreads();   // all frag reads of this buf done before reuse
        buf = (buf + 1 == NBUF) ? 0 : buf + 1;
    }

    #pragma unroll
    for (int fm = 0; fm < 2; fm++) {
        int r0 = wm * 32 + fm * 16 + (lane >> 2);
        int tokA = s_tok[r0];
        int tokB = s_tok[r0 + 8];
        #pragma unroll
        for (int fn = 0; fn < 4; fn++) {
            int c = n0 + wn * 32 + fn * 8 + (lane & 3) * 2;
            if (tokA >= 0)
                *(float2*)(p.out + (size_t)tokA * DPROJ + c) =
                    make_float2(acc[fm][fn][0] * 32.f, acc[fm][fn][1] * 32.f);
            if (tokB >= 0)
                *(float2*)(p.out + (size_t)tokB * DPROJ + c) =
                    make_float2(acc[fm][fn][2] * 32.f, acc[fm][fn][3] * 32.f);
        }
    }
}

extern "C" void kernel_launch(void* const* d_in, const int* in_sizes, int n_in,
                              void* d_out, int out_size) {
    Params p;
    const void* ids = d_in[0];
    p.emb[0]  = (const float*)d_in[1];
    p.proj[0] = (const float*)d_in[2];
    p.emb[1]  = (const float*)d_in[3];
    p.proj[1] = (const float*)d_in[4];
    p.emb[2]  = (const float*)d_in[5];
    p.proj[2] = (const float*)d_in[6];
    p.emb[3]  = (const float*)d_in[7];
    p.proj[3] = (const float*)d_in[8];
    p.out = (float*)d_out;

    cudaFuncSetAttribute(gemm_kernel, cudaFuncAttributeMaxDynamicSharedMemorySize, GEMM_SMEM);

    conv_proj_kernel<<<dim3(512, 4), 256>>>(p);          // also zeroes g_cnt
    bucketize_kernel<<<NTOK / 256, 256>>>(ids);          // self-detecting id layout
    gather_emb_kernel<<<dim3(512, 4), 256>>>(p);
    gemm_kernel<<<dim3(131, DPROJ / 128), 512, GEMM_SMEM>>>(p);
}

// round 10
// speedup vs baseline: 3.0498x; 1.0678x over previous
#include <cuda_runtime.h>
#include <cuda_bf16.h>
#include <cstdint>

// S4 adaptive embedding: bf16 hi/lo split mma.sync + cp.async.bulk staged GEMM.
// R10: block tile 128x256 (warp 32x64), B-resident path for small-K buckets 2/3,
// streaming double-buffer path for buckets 0/1.

#define NTOK  16384
#define NTOKP 16512
#define DPROJ 1024
#define NB2   16
#define NB3   4

__device__ int g_cnt[4];
__device__ int g_tok[4][NTOK];
__device__ int g_idx[4][NTOK];

__device__ alignas(128) __nv_bfloat16 g_embH[(size_t)NTOKP * 1408];
__device__ alignas(128) __nv_bfloat16 g_embL[(size_t)NTOKP * 1408];
__device__ alignas(128) __nv_bfloat16 g_projH[(size_t)DPROJ * 1408];
__device__ alignas(128) __nv_bfloat16 g_projL[(size_t)DPROJ * 1408];

__constant__ int c_D[4]    = {1024, 256, 64, 16};
__constant__ int c_Dpad[4] = {1024, 256, 64, 64};
__constant__ int c_lgD[4]  = {10, 8, 6, 4};
__constant__ int c_KO[4]   = {0, 1024, 1280, 1344};

struct Params {
    const float* emb[4];
    const float* proj[4];
    float* out;
};

__device__ __forceinline__ uint32_t swz(uint32_t off) { return off ^ ((off >> 3) & 0x70); }

__device__ __forceinline__ uint32_t pack_hi(float x, float y) {
    __nv_bfloat162 t;
    t.x = __float2bfloat16(x);
    t.y = __float2bfloat16(y);
    return *reinterpret_cast<uint32_t*>(&t);
}
__device__ __forceinline__ uint32_t pack_lo(float x, float y) {
    __nv_bfloat16 hx = __float2bfloat16(x), hy = __float2bfloat16(y);
    __nv_bfloat162 t;
    t.x = __float2bfloat16(x - __bfloat162float(hx));
    t.y = __float2bfloat16(y - __bfloat162float(hy));
    return *reinterpret_cast<uint32_t*>(&t);
}

// ---------------- prepasses (layouts identical to R9) ----------------
__global__ void conv_proj_kernel(Params p) {
    if (blockIdx.x == 0 && blockIdx.y == 0 && threadIdx.x < 4) g_cnt[threadIdx.x] = 0;
    int b = blockIdx.y;
    int D = c_D[b], lgG = c_lgD[b] - 3, G = 1 << lgG, ncb = c_Dpad[b] >> 6;
    const float* src = p.proj[b];
    size_t PB = 2ull * c_KO[b] * DPROJ;
    int total = DPROJ << lgG;
    for (int t = blockIdx.x * 256 + threadIdx.x; t < total; t += gridDim.x * 256) {
        int d = t >> lgG, g8 = t & (G - 1);
        int k0 = g8 << 3;
        const float* s = src + (size_t)d * D + k0;
        float4 va = *(const float4*)s, vb2 = *(const float4*)(s + 4);
        uint4 H = make_uint4(pack_hi(va.x, va.y), pack_hi(va.z, va.w),
                             pack_hi(vb2.x, vb2.y), pack_hi(vb2.z, vb2.w));
        uint4 L = make_uint4(pack_lo(va.x, va.y), pack_lo(va.z, va.w),
                             pack_lo(vb2.x, vb2.y), pack_lo(vb2.z, vb2.w));
        int nt = d >> 7, r = d & 127, ck = k0 >> 6;
        size_t off = PB + (size_t)(nt * ncb + ck) * 16384
                        + swz((uint32_t)(r * 128 + ((g8 & 7) << 4)));
        *(uint4*)((char*)g_projH + off) = H;
        *(uint4*)((char*)g_projL + off) = L;
    }
}

__global__ void bucketize_kernel(const void* ids_raw) {
    const int* w = (const int*)ids_raw;
    int nz = w[2 * threadIdx.x + 1];
    int is64 = (__syncthreads_or(nz) == 0);
    int i = blockIdx.x * 256 + threadIdx.x;
    long long id = is64 ? ((const long long*)ids_raw)[i] : (long long)w[i];
    int b, l;
    if (id < 20000)       { b = 0; l = 0; }
    else if (id < 40000)  { b = 1; l = 20000; }
    else if (id < 200000) { b = 2; l = 40000; }
    else                  { b = 3; l = 200000; }
    int slot = atomicAdd(&g_cnt[b], 1);
    g_tok[b][slot] = i;
    g_idx[b][slot] = (int)(id - l);
}

__global__ void gather_emb_kernel(Params p) {
    int b = blockIdx.y;
    int cnt = g_cnt[b], D = c_D[b], lgG = c_lgD[b] - 3, G = 1 << lgG, ncb = c_Dpad[b] >> 6;
    const float* src = p.emb[b];
    size_t AB = 2ull * c_KO[b] * NTOKP;
    int total = cnt << lgG;
    for (int t = blockIdx.x * 256 + threadIdx.x; t < total; t += gridDim.x * 256) {
        int slot = t >> lgG, g8 = t & (G - 1);
        int k0 = g8 << 3;
        const float* s = src + (size_t)g_idx[b][slot] * D + k0;
        float4 va = *(const float4*)s, vb2 = *(const float4*)(s + 4);
        uint4 H = make_uint4(pack_hi(va.x, va.y), pack_hi(va.z, va.w),
                             pack_hi(vb2.x, vb2.y), pack_hi(vb2.z, vb2.w));
        uint4 L = make_uint4(pack_lo(va.x, va.y), pack_lo(va.z, va.w),
                             pack_lo(vb2.x, vb2.y), pack_lo(vb2.z, vb2.w));
        int mt = slot >> 7, r = slot & 127, ck = k0 >> 6;
        size_t off = AB + (size_t)(mt * ncb + ck) * 16384
                        + swz((uint32_t)(r * 128 + ((g8 & 7) << 4)));
        *(uint4*)((char*)g_embH + off) = H;
        *(uint4*)((char*)g_embL + off) = L;
    }
}

// ---------------- MMA / bulk-copy helpers ----------------
#define LDSM_X4(r, addr) \
    asm volatile("ldmatrix.sync.aligned.m8n8.x4.shared.b16 {%0,%1,%2,%3}, [%4];" \
        : "=r"((r)[0]), "=r"((r)[1]), "=r"((r)[2]), "=r"((r)[3]) : "r"(addr))

#define MMA_BF16(c, a, b0, b1) \
    asm volatile("mma.sync.aligned.m16n8k16.row.col.f32.bf16.bf16.f32 " \
        "{%0,%1,%2,%3}, {%4,%5,%6,%7}, {%8,%9}, {%0,%1,%2,%3};" \
        : "+f"((c)[0]), "+f"((c)[1]), "+f"((c)[2]), "+f"((c)[3]) \
        : "r"((a)[0]), "r"((a)[1]), "r"((a)[2]), "r"((a)[3]), "r"(b0), "r"(b1))

#define CP_BULK(dst, src, bytes, mbar) \
    asm volatile("cp.async.bulk.shared::cta.global.mbarrier::complete_tx::bytes [%0], [%1], %2, [%3];" \
        :: "r"(dst), "l"(src), "r"((uint32_t)(bytes)), "r"(mbar) : "memory")
#define MBAR_INIT(a, c) \
    asm volatile("mbarrier.init.shared.b64 [%0], %1;" :: "r"(a), "r"((uint32_t)(c)) : "memory")
#define MBAR_EXPECT(a, n) \
    asm volatile("mbarrier.arrive.expect_tx.shared.b64 _, [%0], %1;" :: "r"(a), "r"((uint32_t)(n)) : "memory")
#define MBAR_WAIT(a, ph) do { \
    uint32_t _m = (a), _p = (ph), _d; \
    asm volatile("{ .reg .pred p; mbarrier.try_wait.parity.acquire.cta.shared::cta.b64 p, [%1], %2; selp.b32 %0,1,0,p; }" \
        : "=r"(_d) : "r"(_m), "r"(_p) : "memory"); \
    if (!_d) { \
        asm volatile("{ .reg .pred P1; WL_%=: mbarrier.try_wait.parity.acquire.cta.shared::cta.b64 P1, [%0], %1, 0x989680; " \
                     "@P1 bra.uni WD_%=; bra.uni WL_%=; WD_%=: }" :: "r"(_m), "r"(_p) : "memory"); \
    } } while (0)

__device__ __forceinline__ uint32_t smem_u32(const void* p) {
    uint32_t a;
    asm("{ .reg .u64 t; cvta.to.shared.u64 t, %1; cvt.u32.u64 %0, t; }" : "=r"(a) : "l"(p));
    return a;
}

// smem stages: [AH 16K | AL 16K | BH 32K | BL 32K] @ 0 and @ 96K; mbars @ 192K
#define STAGEB  98304
#define SM_MBAR 196608
#define GEMM_SMEM 196640

__global__ void __launch_bounds__(512, 1) gemm_kernel(Params p) {
    extern __shared__ __align__(1024) char sm[];
    const int tid  = threadIdx.x;
    const int lane = tid & 31;
    const int wid  = tid >> 5;
    const int wm   = wid >> 2;       // M strip (32 rows)
    const int wn   = wid & 3;        // N strip (64 cols)

    // ---- decode blockIdx.x -> (bucket, mtile range) ----
    int cnt0 = g_cnt[0], cnt1 = g_cnt[1], cnt2 = g_cnt[2], cnt3 = g_cnt[3];
    int t0 = (cnt0 + 127) >> 7, t1 = (cnt1 + 127) >> 7;
    int t2 = (cnt2 + 127) >> 7, t3 = (cnt3 + 127) >> 7;
    int x = blockIdx.x, b, n, mts, mte;
    if (x < t0)               { b = 0; n = cnt0; mts = x; mte = x + 1; }
    else if ((x -= t0) < t1)  { b = 1; n = cnt1; mts = x; mte = x + 1; }
    else if ((x -= t1) < NB2) { b = 2; n = cnt2; int bs = (t2 + NB2 - 1) / NB2;
                                mts = x * bs; mte = min(mts + bs, t2); }
    else if ((x -= NB2) < NB3){ b = 3; n = cnt3; int bs = (t3 + NB3 - 1) / NB3;
                                mts = x * bs; mte = min(mts + bs, t3); }
    else return;
    if (mts >= mte) return;

    const int np = blockIdx.y;            // 256-col group
    const int ncb = c_Dpad[b] >> 6;       // {16,4,1,1}
    const int ksteps = (b == 3) ? 1 : 4;
    const bool resident = (b >= 2);

    const char* pAH = (const char*)g_embH + 2ull * c_KO[b] * NTOKP;
    const char* pAL = (const char*)g_embL + 2ull * c_KO[b] * NTOKP;
    const char* pBH = (const char*)g_projH + 2ull * c_KO[b] * DPROJ;
    const char* pBL = (const char*)g_projL + 2ull * c_KO[b] * DPROJ;

    const uint32_t sb = smem_u32(sm);
    const uint32_t mb[2] = {sb + SM_MBAR, sb + SM_MBAR + 8};
    if (tid == 0) { MBAR_INIT(mb[0], 1); MBAR_INIT(mb[1], 1); }
    __syncthreads();
    int ph[2] = {0, 0};

    // per-lane fragment address pieces
    const uint32_t a_row = wm * 32 + (lane & 15);
    const uint32_t a_kof2 = ((lane >> 1) & 8) * 2;
    const int gq = lane >> 3;
    const uint32_t b_row0 = wn * 64 + ((gq >> 1) & 1) * 8 + (lane & 7);
    const uint32_t b_kof2 = (gq & 1) * 16;

    float acc[2][8][4];

    // ---- compute one K-64 chunk from aBase/bBase ----
    auto do_kstep = [&](int ks, uint32_t aBase, uint32_t bBase) {
        const uint32_t kb = ks * 32;
        uint32_t af[2][2][4];
        #pragma unroll
        for (int fm = 0; fm < 2; fm++) {
            uint32_t off = swz((a_row + fm * 16) * 128 + kb + a_kof2);
            LDSM_X4(af[0][fm], aBase + off);
            LDSM_X4(af[1][fm], aBase + 16384 + off);
        }
        #pragma unroll
        for (int half = 0; half < 2; half++) {
            uint32_t bfr[2][2][4];
            #pragma unroll
            for (int j = 0; j < 2; j++) {
                uint32_t r = b_row0 + (half * 2 + j) * 16;
                uint32_t off = ((r >> 7) << 14) + swz((r & 127) * 128 + kb + b_kof2);
                LDSM_X4(bfr[0][j], bBase + off);            // BH
                LDSM_X4(bfr[1][j], bBase + 32768 + off);    // BL
            }
            #pragma unroll
            for (int fm = 0; fm < 2; fm++)
                #pragma unroll
                for (int f = 0; f < 4; f++) {
                    float* c = acc[fm][half * 4 + f];
                    uint32_t b0h = bfr[0][f >> 1][(f & 1) * 2];
                    uint32_t b1h = bfr[0][f >> 1][(f & 1) * 2 + 1];
                    uint32_t b0l = bfr[1][f >> 1][(f & 1) * 2];
                    uint32_t b1l = bfr[1][f >> 1][(f & 1) * 2 + 1];
                    MMA_BF16(c, af[0][fm], b0h, b1h);
                    MMA_BF16(c, af[1][fm], b0h, b1h);
                    MMA_BF16(c, af[0][fm], b0l, b1l);
                }
        }
    };

    auto epilogue = [&](int mt) {
        int m0 = mt << 7;
        #pragma unroll
        for (int fm = 0; fm < 2; fm++) {
            int r0 = wm * 32 + fm * 16 + (lane >> 2);
            int mA = m0 + r0, mB = m0 + r0 + 8;
            int tokA = (mA < n) ? g_tok[b][mA] : -1;
            int tokB = (mB < n) ? g_tok[b][mB] : -1;
            #pragma unroll
            for (int fn = 0; fn < 8; fn++) {
                int c = np * 256 + wn * 64 + fn * 8 + (lane & 3) * 2;
                if (tokA >= 0)
                    *(float2*)(p.out + (size_t)tokA * DPROJ + c) =
                        make_float2(acc[fm][fn][0] * 32.f, acc[fm][fn][1] * 32.f);
                if (tokB >= 0)
                    *(float2*)(p.out + (size_t)tokB * DPROJ + c) =
                        make_float2(acc[fm][fn][2] * 32.f, acc[fm][fn][3] * 32.f);
            }
        }
    };

    auto issue_B = [&](int ck, uint32_t stg, uint32_t bar) {     // 64KB
        uint32_t d = sb + stg * STAGEB + 32768;
        size_t o0 = (size_t)((2 * np) * ncb + ck) * 16384;
        size_t o1 = (size_t)((2 * np + 1) * ncb + ck) * 16384;
        CP_BULK(d,          pBH + o0, 16384, bar);
        CP_BULK(d + 16384,  pBH + o1, 16384, bar);
        CP_BULK(d + 32768,  pBL + o0, 16384, bar);
        CP_BULK(d + 49152,  pBL + o1, 16384, bar);
    };
    auto issue_A = [&](int mt, int ck, uint32_t stg, uint32_t bar) {  // 32KB
        uint32_t d = sb + stg * STAGEB;
        size_t o = (size_t)(mt * ncb + ck) * 16384;
        CP_BULK(d,         pAH + o, 16384, bar);
        CP_BULK(d + 16384, pAL + o, 16384, bar);
    };

    if (!resident) {
        // ---- streaming path (b0/b1): one mtile, double-buffered 96KB chunks ----
        const int mt = mts;
        #pragma unroll
        for (int fm = 0; fm < 2; fm++)
            #pragma unroll
            for (int fn = 0; fn < 8; fn++)
                #pragma unroll
                for (int r = 0; r < 4; r++) acc[fm][fn][r] = 0.f;

        if (tid == 0) {
            MBAR_EXPECT(mb[0], 98304);
            issue_A(mt, 0, 0, mb[0]);
            issue_B(0, 0, mb[0]);
        }
        for (int ck = 0; ck < ncb; ck++) {
            const int stg = ck & 1;
            if (ck + 1 < ncb && tid == 0) {
                MBAR_EXPECT(mb[stg ^ 1], 98304);
                issue_A(mt, ck + 1, stg ^ 1, mb[stg ^ 1]);
                issue_B(ck + 1, stg ^ 1, mb[stg ^ 1]);
            }
            MBAR_WAIT(mb[stg], ph[stg]);
            ph[stg] ^= 1;
            uint32_t base = sb + stg * STAGEB;
            do_kstep(0, base, base + 32768);
            do_kstep(1, base, base + 32768);
            do_kstep(2, base, base + 32768);
            do_kstep(3, base, base + 32768);
            __syncthreads();
        }
        epilogue(mt);
    } else {
        // ---- resident path (b2/b3): B loaded once, A double-buffered over mtiles ----
        if (tid == 0) {
            MBAR_EXPECT(mb[0], 98304);
            issue_B(0, 0, mb[0]);          // resident B lives in stage0's B slot
            issue_A(mts, 0, 0, mb[0]);
        }
        const uint32_t bBase = sb + 32768;
        for (int i = 0, mt = mts; mt < mte; i++, mt++) {
            const int abuf = i & 1;
            if (mt + 1 < mte && tid == 0) {
                MBAR_EXPECT(mb[abuf ^ 1], 32768);
                issue_A(mt + 1, 0, abuf ^ 1, mb[abuf ^ 1]);
            }
            MBAR_WAIT(mb[abuf], ph[abuf]);
            ph[abuf] ^= 1;

            #pragma unroll
            for (int fm = 0; fm < 2; fm++)
                #pragma unroll
                for (int fn = 0; fn < 8; fn++)
                    #pragma unroll
                    for (int r = 0; r < 4; r++) acc[fm][fn][r] = 0.f;

            uint32_t aBase = sb + abuf * STAGEB;
            if (ksteps == 4) {
                do_kstep(0, aBase, bBase);
                do_kstep(1, aBase, bBase);
                do_kstep(2, aBase, bBase);
                do_kstep(3, aBase, bBase);
            } else {
                do_kstep(0, aBase, bBase);
            }
            epilogue(mt);
            __syncthreads();
        }
    }
}

extern "C" void kernel_launch(void* const* d_in, const int* in_sizes, int n_in,
                              void* d_out, int out_size) {
    Params p;
    const void* ids = d_in[0];
    p.emb[0]  = (const float*)d_in[1];
    p.proj[0] = (const float*)d_in[2];
    p.emb[1]  = (const float*)d_in[3];
    p.proj[1] = (const float*)d_in[4];
    p.emb[2]  = (const float*)d_in[5];
    p.proj[2] = (const float*)d_in[6];
    p.emb[3]  = (const float*)d_in[7];
    p.proj[3] = (const float*)d_in[8];
    p.out = (float*)d_out;

    cudaFuncSetAttribute(gemm_kernel, cudaFuncAttributeMaxDynamicSharedMemorySize, GEMM_SMEM);

    conv_proj_kernel<<<dim3(512, 4), 256>>>(p);
    bucketize_kernel<<<NTOK / 256, 256>>>(ids);
    gather_emb_kernel<<<dim3(512, 4), 256>>>(p);
    gemm_kernel<<<dim3(150, 4), 512, GEMM_SMEM>>>(p);
}

// round 11
// speedup vs baseline: 3.4357x; 1.1265x over previous
#include <cuda_runtime.h>
#include <cuda_bf16.h>
#include <cstdint>

// S4 adaptive embedding: bf16 hi/lo split mma.sync + cp.async.bulk staged GEMM.
// R11: block tile 64x128 (256 thr, warp 32x32), 48KB stages x2 = 96KB smem
// -> 2 CTAs/SM for cross-CTA latency hiding. Resident-B path for buckets 2/3.

#define NTOK  16384
#define NTOKP 16512
#define DPROJ 1024
#define NB2   24
#define NB3   8

__device__ int g_cnt[4];
__device__ int g_tok[4][NTOK];
__device__ int g_idx[4][NTOK];

__device__ alignas(128) __nv_bfloat16 g_embH[(size_t)NTOKP * 1408];
__device__ alignas(128) __nv_bfloat16 g_embL[(size_t)NTOKP * 1408];
__device__ alignas(128) __nv_bfloat16 g_projH[(size_t)DPROJ * 1408];
__device__ alignas(128) __nv_bfloat16 g_projL[(size_t)DPROJ * 1408];

__constant__ int c_D[4]    = {1024, 256, 64, 16};
__constant__ int c_Dpad[4] = {1024, 256, 64, 64};
__constant__ int c_lgD[4]  = {10, 8, 6, 4};
__constant__ int c_KO[4]   = {0, 1024, 1280, 1344};

struct Params {
    const float* emb[4];
    const float* proj[4];
    float* out;
};

__device__ __forceinline__ uint32_t swz(uint32_t off) { return off ^ ((off >> 3) & 0x70); }

__device__ __forceinline__ uint32_t pack_hi(float x, float y) {
    __nv_bfloat162 t;
    t.x = __float2bfloat16(x);
    t.y = __float2bfloat16(y);
    return *reinterpret_cast<uint32_t*>(&t);
}
__device__ __forceinline__ uint32_t pack_lo(float x, float y) {
    __nv_bfloat16 hx = __float2bfloat16(x), hy = __float2bfloat16(y);
    __nv_bfloat162 t;
    t.x = __float2bfloat16(x - __bfloat162float(hx));
    t.y = __float2bfloat16(y - __bfloat162float(hy));
    return *reinterpret_cast<uint32_t*>(&t);
}

// ---------------- prepasses ----------------
// proj: 128-row x 64k units (16KB), SW128. Also zeroes counters.
__global__ void conv_proj_kernel(Params p) {
    if (blockIdx.x == 0 && blockIdx.y == 0 && threadIdx.x < 4) g_cnt[threadIdx.x] = 0;
    int b = blockIdx.y;
    int D = c_D[b], lgG = c_lgD[b] - 3, G = 1 << lgG, ncb = c_Dpad[b] >> 6;
    const float* src = p.proj[b];
    size_t PB = 2ull * c_KO[b] * DPROJ;
    int total = DPROJ << lgG;
    for (int t = blockIdx.x * 256 + threadIdx.x; t < total; t += gridDim.x * 256) {
        int d = t >> lgG, g8 = t & (G - 1);
        int k0 = g8 << 3;
        const float* s = src + (size_t)d * D + k0;
        float4 va = *(const float4*)s, vb2 = *(const float4*)(s + 4);
        uint4 H = make_uint4(pack_hi(va.x, va.y), pack_hi(va.z, va.w),
                             pack_hi(vb2.x, vb2.y), pack_hi(vb2.z, vb2.w));
        uint4 L = make_uint4(pack_lo(va.x, va.y), pack_lo(va.z, va.w),
                             pack_lo(vb2.x, vb2.y), pack_lo(vb2.z, vb2.w));
        int nt = d >> 7, r = d & 127, ck = k0 >> 6;
        size_t off = PB + (size_t)(nt * ncb + ck) * 16384
                        + swz((uint32_t)(r * 128 + ((g8 & 7) << 4)));
        *(uint4*)((char*)g_projH + off) = H;
        *(uint4*)((char*)g_projL + off) = L;
    }
}

__global__ void bucketize_kernel(const void* ids_raw) {
    const int* w = (const int*)ids_raw;
    int nz = w[2 * threadIdx.x + 1];
    int is64 = (__syncthreads_or(nz) == 0);
    int i = blockIdx.x * 256 + threadIdx.x;
    long long id = is64 ? ((const long long*)ids_raw)[i] : (long long)w[i];
    int b, l;
    if (id < 20000)       { b = 0; l = 0; }
    else if (id < 40000)  { b = 1; l = 20000; }
    else if (id < 200000) { b = 2; l = 40000; }
    else                  { b = 3; l = 200000; }
    int slot = atomicAdd(&g_cnt[b], 1);
    g_tok[b][slot] = i;
    g_idx[b][slot] = (int)(id - l);
}

// emb: 64-row x 64k units (8KB), SW128 on 128B rows.
__global__ void gather_emb_kernel(Params p) {
    int b = blockIdx.y;
    int cnt = g_cnt[b], D = c_D[b], lgG = c_lgD[b] - 3, G = 1 << lgG, ncb = c_Dpad[b] >> 6;
    const float* src = p.emb[b];
    size_t AB = 2ull * c_KO[b] * NTOKP;
    int total = cnt << lgG;
    for (int t = blockIdx.x * 256 + threadIdx.x; t < total; t += gridDim.x * 256) {
        int slot = t >> lgG, g8 = t & (G - 1);
        int k0 = g8 << 3;
        const float* s = src + (size_t)g_idx[b][slot] * D + k0;
        float4 va = *(const float4*)s, vb2 = *(const float4*)(s + 4);
        uint4 H = make_uint4(pack_hi(va.x, va.y), pack_hi(va.z, va.w),
                             pack_hi(vb2.x, vb2.y), pack_hi(vb2.z, vb2.w));
        uint4 L = make_uint4(pack_lo(va.x, va.y), pack_lo(va.z, va.w),
                             pack_lo(vb2.x, vb2.y), pack_lo(vb2.z, vb2.w));
        int mt = slot >> 6, r = slot & 63, ck = k0 >> 6;
        size_t off = AB + (size_t)(mt * ncb + ck) * 8192
                        + swz((uint32_t)(r * 128 + ((g8 & 7) << 4)));
        *(uint4*)((char*)g_embH + off) = H;
        *(uint4*)((char*)g_embL + off) = L;
    }
}

// ---------------- MMA / bulk-copy helpers ----------------
#define LDSM_X4(r, addr) \
    asm volatile("ldmatrix.sync.aligned.m8n8.x4.shared.b16 {%0,%1,%2,%3}, [%4];" \
        : "=r"((r)[0]), "=r"((r)[1]), "=r"((r)[2]), "=r"((r)[3]) : "r"(addr))

#define MMA_BF16(c, a, b0, b1) \
    asm volatile("mma.sync.aligned.m16n8k16.row.col.f32.bf16.bf16.f32 " \
        "{%0,%1,%2,%3}, {%4,%5,%6,%7}, {%8,%9}, {%0,%1,%2,%3};" \
        : "+f"((c)[0]), "+f"((c)[1]), "+f"((c)[2]), "+f"((c)[3]) \
        : "r"((a)[0]), "r"((a)[1]), "r"((a)[2]), "r"((a)[3]), "r"(b0), "r"(b1))

#define CP_BULK(dst, src, bytes, mbar) \
    asm volatile("cp.async.bulk.shared::cta.global.mbarrier::complete_tx::bytes [%0], [%1], %2, [%3];" \
        :: "r"(dst), "l"(src), "r"((uint32_t)(bytes)), "r"(mbar) : "memory")
#define MBAR_INIT(a, c) \
    asm volatile("mbarrier.init.shared.b64 [%0], %1;" :: "r"(a), "r"((uint32_t)(c)) : "memory")
#define MBAR_EXPECT(a, n) \
    asm volatile("mbarrier.arrive.expect_tx.shared.b64 _, [%0], %1;" :: "r"(a), "r"((uint32_t)(n)) : "memory")
#define MBAR_WAIT(a, ph) do { \
    uint32_t _m = (a), _p = (ph), _d; \
    asm volatile("{ .reg .pred p; mbarrier.try_wait.parity.acquire.cta.shared::cta.b64 p, [%1], %2; selp.b32 %0,1,0,p; }" \
        : "=r"(_d) : "r"(_m), "r"(_p) : "memory"); \
    if (!_d) { \
        asm volatile("{ .reg .pred P1; WL_%=: mbarrier.try_wait.parity.acquire.cta.shared::cta.b64 P1, [%0], %1, 0x989680; " \
                     "@P1 bra.uni WD_%=; bra.uni WL_%=; WD_%=: }" :: "r"(_m), "r"(_p) : "memory"); \
    } } while (0)

__device__ __forceinline__ uint32_t smem_u32(const void* p) {
    uint32_t a;
    asm("{ .reg .u64 t; cvta.to.shared.u64 t, %1; cvt.u32.u64 %0, t; }" : "=r"(a) : "l"(p));
    return a;
}

// stage (48KB): AH@0(8K) AL@8K BH@16K(16K) BL@32K ; 2 stages; mbars after
#define STAGEB  49152
#define SM_MBAR 98304
#define GEMM_SMEM 98320

__global__ void __launch_bounds__(256, 2) gemm_kernel(Params p) {
    extern __shared__ __align__(1024) char sm[];
    const int tid  = threadIdx.x;
    const int lane = tid & 31;
    const int wid  = tid >> 5;
    const int wm   = wid >> 2;       // 0..1 -> 32-row strip
    const int wn   = wid & 3;        // 0..3 -> 32-col strip

    // decode blockIdx.x -> (bucket, m-unit range), 64-row units
    int cnt0 = g_cnt[0], cnt1 = g_cnt[1], cnt2 = g_cnt[2], cnt3 = g_cnt[3];
    int t0 = (cnt0 + 63) >> 6, t1 = (cnt1 + 63) >> 6;
    int t2 = (cnt2 + 63) >> 6, t3 = (cnt3 + 63) >> 6;
    int x = blockIdx.x, b, n, mts, mte;
    if (x < t0)               { b = 0; n = cnt0; mts = x; mte = x + 1; }
    else if ((x -= t0) < t1)  { b = 1; n = cnt1; mts = x; mte = x + 1; }
    else if ((x -= t1) < NB2) { b = 2; n = cnt2; int bs = (t2 + NB2 - 1) / NB2;
                                mts = x * bs; mte = min(mts + bs, t2); }
    else if ((x -= NB2) < NB3){ b = 3; n = cnt3; int bs = (t3 + NB3 - 1) / NB3;
                                mts = x * bs; mte = min(mts + bs, t3); }
    else return;
    if (mts >= mte) return;

    const int np = blockIdx.y;           // 128-col group
    const int ncb = c_Dpad[b] >> 6;
    const int ksteps = (b == 3) ? 1 : 4;
    const bool resident = (b >= 2);

    const char* pAH = (const char*)g_embH + 2ull * c_KO[b] * NTOKP;
    const char* pAL = (const char*)g_embL + 2ull * c_KO[b] * NTOKP;
    const char* pBH = (const char*)g_projH + 2ull * c_KO[b] * DPROJ;
    const char* pBL = (const char*)g_projL + 2ull * c_KO[b] * DPROJ;

    const uint32_t sb = smem_u32(sm);
    const uint32_t mb[2] = {sb + SM_MBAR, sb + SM_MBAR + 8};
    if (tid == 0) { MBAR_INIT(mb[0], 1); MBAR_INIT(mb[1], 1); }
    __syncthreads();
    int ph[2] = {0, 0};

    const uint32_t a_row = wm * 32 + (lane & 15);
    const uint32_t a_kof2 = ((lane >> 1) & 8) * 2;
    const int gq = lane >> 3;
    const uint32_t b_row0 = wn * 32 + ((gq >> 1) & 1) * 8 + (lane & 7);
    const uint32_t b_kof2 = (gq & 1) * 16;

    float acc[2][4][4];

    auto clear_acc = [&]() {
        #pragma unroll
        for (int fm = 0; fm < 2; fm++)
            #pragma unroll
            for (int fn = 0; fn < 4; fn++)
                #pragma unroll
                for (int r = 0; r < 4; r++) acc[fm][fn][r] = 0.f;
    };

    auto do_kstep = [&](int ks, uint32_t aBase, uint32_t bBase) {
        const uint32_t kb = ks * 32;
        uint32_t af[2][2][4];
        #pragma unroll
        for (int fm = 0; fm < 2; fm++) {
            uint32_t off = swz((a_row + fm * 16) * 128 + kb + a_kof2);
            LDSM_X4(af[0][fm], aBase + off);          // AH
            LDSM_X4(af[1][fm], aBase + 8192 + off);   // AL
        }
        uint32_t bfr[2][2][4];
        #pragma unroll
        for (int j = 0; j < 2; j++) {
            uint32_t off = swz((b_row0 + j * 16) * 128 + kb + b_kof2);
            LDSM_X4(bfr[0][j], bBase + off);          // BH
            LDSM_X4(bfr[1][j], bBase + 16384 + off);  // BL
        }
        #pragma unroll
        for (int fm = 0; fm < 2; fm++)
            #pragma unroll
            for (int f = 0; f < 4; f++) {
                float* c = acc[fm][f];
                uint32_t b0h = bfr[0][f >> 1][(f & 1) * 2];
                uint32_t b1h = bfr[0][f >> 1][(f & 1) * 2 + 1];
                uint32_t b0l = bfr[1][f >> 1][(f & 1) * 2];
                uint32_t b1l = bfr[1][f >> 1][(f & 1) * 2 + 1];
                MMA_BF16(c, af[0][fm], b0h, b1h);
                MMA_BF16(c, af[1][fm], b0h, b1h);
                MMA_BF16(c, af[0][fm], b0l, b1l);
            }
    };

    auto epilogue = [&](int mt) {
        int m0 = mt << 6;
        #pragma unroll
        for (int fm = 0; fm < 2; fm++) {
            int r0 = wm * 32 + fm * 16 + (lane >> 2);
            int mA = m0 + r0, mB = m0 + r0 + 8;
            int tokA = (mA < n) ? g_tok[b][mA] : -1;
            int tokB = (mB < n) ? g_tok[b][mB] : -1;
            #pragma unroll
            for (int fn = 0; fn < 4; fn++) {
                int c = np * 128 + wn * 32 + fn * 8 + (lane & 3) * 2;
                if (tokA >= 0)
                    *(float2*)(p.out + (size_t)tokA * DPROJ + c) =
                        make_float2(acc[fm][fn][0] * 32.f, acc[fm][fn][1] * 32.f);
                if (tokB >= 0)
                    *(float2*)(p.out + (size_t)tokB * DPROJ + c) =
                        make_float2(acc[fm][fn][2] * 32.f, acc[fm][fn][3] * 32.f);
            }
        }
    };

    auto issue_A = [&](int mt, int ck, uint32_t stg, uint32_t bar) {   // 16KB
        uint32_t d = sb + stg * STAGEB;
        size_t o = (size_t)(mt * ncb + ck) * 8192;
        CP_BULK(d,        pAH + o, 8192, bar);
        CP_BULK(d + 8192, pAL + o, 8192, bar);
    };
    auto issue_B = [&](int ck, uint32_t stg, uint32_t bar) {           // 32KB
        uint32_t d = sb + stg * STAGEB + 16384;
        size_t o = (size_t)(np * ncb + ck) * 16384;
        CP_BULK(d,         pBH + o, 16384, bar);
        CP_BULK(d + 16384, pBL + o, 16384, bar);
    };

    if (!resident) {
        // streaming (b0/b1): one m-unit, double-buffered 48KB stages
        const int mt = mts;
        clear_acc();
        if (tid == 0) {
            MBAR_EXPECT(mb[0], 49152);
            issue_A(mt, 0, 0, mb[0]);
            issue_B(0, 0, mb[0]);
        }
        for (int ck = 0; ck < ncb; ck++) {
            const int stg = ck & 1;
            if (ck + 1 < ncb && tid == 0) {
                MBAR_EXPECT(mb[stg ^ 1], 49152);
                issue_A(mt, ck + 1, stg ^ 1, mb[stg ^ 1]);
                issue_B(ck + 1, stg ^ 1, mb[stg ^ 1]);
            }
            MBAR_WAIT(mb[stg], ph[stg]);
            ph[stg] ^= 1;
            uint32_t base = sb + stg * STAGEB;
            do_kstep(0, base, base + 16384);
            do_kstep(1, base, base + 16384);
            do_kstep(2, base, base + 16384);
            do_kstep(3, base, base + 16384);
            __syncthreads();
        }
        epilogue(mt);
    } else {
        // resident B (b2/b3): B once into stage0 B-slot; A alternates A-slots
        if (tid == 0) {
            MBAR_EXPECT(mb[0], 49152);
            issue_B(0, 0, mb[0]);
            issue_A(mts, 0, 0, mb[0]);
        }
        const uint32_t bBase = sb + 16384;
        for (int i = 0, mt = mts; mt < mte; i++, mt++) {
            const int abuf = i & 1;
            if (mt + 1 < mte && tid == 0) {
                MBAR_EXPECT(mb[abuf ^ 1], 16384);
                issue_A(mt + 1, 0, abuf ^ 1, mb[abuf ^ 1]);
            }
            MBAR_WAIT(mb[abuf], ph[abuf]);
            ph[abuf] ^= 1;
            clear_acc();
            uint32_t aBase = sb + abuf * STAGEB;
            if (ksteps == 4) {
                do_kstep(0, aBase, bBase);
                do_kstep(1, aBase, bBase);
                do_kstep(2, aBase, bBase);
                do_kstep(3, aBase, bBase);
            } else {
                do_kstep(0, aBase, bBase);
            }
            epilogue(mt);
            __syncthreads();
        }
    }
}

extern "C" void kernel_launch(void* const* d_in, const int* in_sizes, int n_in,
                              void* d_out, int out_size) {
    Params p;
    const void* ids = d_in[0];
    p.emb[0]  = (const float*)d_in[1];
    p.proj[0] = (const float*)d_in[2];
    p.emb[1]  = (const float*)d_in[3];
    p.proj[1] = (const float*)d_in[4];
    p.emb[2]  = (const float*)d_in[5];
    p.proj[2] = (const float*)d_in[6];
    p.emb[3]  = (const float*)d_in[7];
    p.proj[3] = (const float*)d_in[8];
    p.out = (float*)d_out;

    cudaFuncSetAttribute(gemm_kernel, cudaFuncAttributeMaxDynamicSharedMemorySize, GEMM_SMEM);

    conv_proj_kernel<<<dim3(512, 4), 256>>>(p);
    bucketize_kernel<<<NTOK / 256, 256>>>(ids);
    gather_emb_kernel<<<dim3(512, 4), 256>>>(p);
    gemm_kernel<<<dim3(128, DPROJ / 128), 256, GEMM_SMEM>>>(p);
}